// round 7
// baseline (speedup 1.0000x reference)
#include <cuda_runtime.h>

#define A_N 16384
#define R_N 8192
#define DIM 128
#define NB  32
#define AT  32   // atoms per attention block

// Scratch (allocation-free rule: __device__ globals). 16 MB total.
__device__ __align__(256) float g_Q[A_N * DIM];
__device__ __align__(256) float g_K[R_N * DIM];
__device__ __align__(256) float g_V[R_N * DIM];
__device__ int g_rseg[NB + 1];

typedef unsigned long long u64;

__device__ __forceinline__ void ffma2(u64& d, u64 a, u64 b) {
    asm("fma.rn.f32x2 %0, %1, %2, %0;" : "+l"(d) : "l"(a), "l"(b));
}
__device__ __forceinline__ void fmul2(u64& d, u64 a, u64 b) {
    asm("mul.rn.f32x2 %0, %1, %2;" : "=l"(d) : "l"(a), "l"(b));
}
__device__ __forceinline__ u64 pack2(float lo, float hi) {
    u64 d;
    asm("mov.b64 %0, {%1, %2};" : "=l"(d)
        : "r"(__float_as_uint(lo)), "r"(__float_as_uint(hi)));
    return d;
}
__device__ __forceinline__ void unpack2(float& lo, float& hi, u64 v) {
    unsigned int a, b;
    asm("mov.b64 {%0, %1}, %2;" : "=r"(a), "=r"(b) : "l"(v));
    lo = __uint_as_float(a); hi = __uint_as_float(b);
}

// ---------------------------------------------------------------------------
// GEMM: Out[m][n] = sum_k X[m][k] * W[n][k]   (X @ W^T), N=K=128 fixed.
// 256 threads, 32-row x 128-col tile (small tiles => big grid => occupancy).
// Warp w owns rows w*4..w*4+3; lane owns cols lane*4..lane*4+3 (f32x2 accs).
// outsel==0 additionally computes g_rseg in block 0.
// ---------------------------------------------------------------------------
__global__ __launch_bounds__(256) void gemm_nt_kernel(
    const float* __restrict__ X, const float* __restrict__ W, int outsel,
    const int* __restrict__ rb)
{
    __shared__ __align__(16) float Ws[32][132];  // Ws[kk][n], padded stride
    __shared__ __align__(16) float Xs[32][32];   // Xs[row][kk]

    float* Out = (outsel == 0) ? g_Q : (outsel == 1) ? g_K : g_V;

    int t = threadIdx.x;
    int lane = t & 31;
    int w = t >> 5;
    int row0 = blockIdx.x * 32;

    u64 acc[4][2];
#pragma unroll
    for (int i = 0; i < 4; i++) { acc[i][0] = 0ull; acc[i][1] = 0ull; }

    for (int kc = 0; kc < 128; kc += 32) {
#pragma unroll
        for (int j = 0; j < 16; j++) {
            int idx = t + j * 256;          // 0..4095
            int n = idx >> 5, kk = idx & 31;
            Ws[kk][n] = W[n * 128 + kc + kk];
        }
#pragma unroll
        for (int j = 0; j < 4; j++) {
            int idx = t + j * 256;          // 0..1023
            int row = idx >> 5, kk = idx & 31;
            Xs[row][kk] = X[(row0 + row) * 128 + kc + kk];
        }
        __syncthreads();

#pragma unroll 8
        for (int kk = 0; kk < 32; kk++) {
            ulonglong2 w2 = *(const ulonglong2*)&Ws[kk][lane * 4];
#pragma unroll
            for (int i = 0; i < 4; i++) {
                float x = Xs[w * 4 + i][kk];   // warp-broadcast LDS
                u64 x2 = pack2(x, x);
                ffma2(acc[i][0], x2, w2.x);
                ffma2(acc[i][1], x2, w2.y);
            }
        }
        __syncthreads();
    }

#pragma unroll
    for (int i = 0; i < 4; i++) {
        ulonglong2 o; o.x = acc[i][0]; o.y = acc[i][1];
        *(ulonglong2*)&Out[(row0 + w * 4 + i) * 128 + lane * 4] = o;
    }

    // Segment boundaries (Q pass, block 0): g_rseg[b] = lower_bound(rb, b).
    if (outsel == 0 && blockIdx.x == 0 && t <= NB) {
        int b = t, lo = 0, hi = R_N;
        while (lo < hi) {
            int mid = (lo + hi) >> 1;
            if (rb[mid] < b) lo = mid + 1; else hi = mid;
        }
        g_rseg[b] = lo;
    }
}

// ---------------------------------------------------------------------------
// Attention: 32 atoms/block (grid 512 => ~3 CTAs/SM), 256 threads, 32-residue
// K/V tiles, online softmax. Warp w owns atoms w*4..w*4+3.
//   scores: lane = residue in tile;   PV/out: lane = dim quad (lane*4..+3)
// Ps stored pre-splatted as u64 (p,p) so PV reads are direct FFMA2 operands.
// ---------------------------------------------------------------------------
__global__ __launch_bounds__(256, 3) void attn_kernel(
    const float* __restrict__ atom_h,
    const int* __restrict__ atom_batch,
    const int* __restrict__ residue_batch,
    float* __restrict__ out)
{
    extern __shared__ float sm[];
    float* Qs = sm;                       // 32*128 floats (16KB)
    float* Ks = Qs + AT * 128;            // 32*132 (padded, 16B-aligned rows)
    float* Vs = Ks + 32 * 132;            // 32*128
    u64*   Ps2 = (u64*)(Vs + 32 * 128);   // 32 atoms * 32 res, (p,p) splats
    int*   ab  = (int*)(Ps2 + AT * 32);   // 32
    int*   rbs = ab + AT;                 // 32

    int t = threadIdx.x;
    int lane = t & 31;
    int w = t >> 5;
    int a0 = blockIdx.x * AT;

    // Load Q tile (32*128 floats = 1024 float4, 4 per thread).
    {
        const float4* src = (const float4*)(g_Q + a0 * 128);
        float4* dst = (float4*)Qs;
#pragma unroll
        for (int j = 0; j < 4; j++) dst[t + j * 256] = src[t + j * 256];
    }
    if (t < AT) ab[t] = atom_batch[a0 + t];
    __syncthreads();

    // Sorted batches => block's residue union is one contiguous interval.
    int r0 = g_rseg[ab[0]];
    int r1 = g_rseg[ab[AT - 1] + 1];

    u64 acc[4][2];
    float mcur[4], lsum[4];
    int myb[4];
#pragma unroll
    for (int i = 0; i < 4; i++) {
        acc[i][0] = 0ull; acc[i][1] = 0ull;
        mcur[i] = -1e30f;
        lsum[i] = 0.f;
        myb[i] = ab[w * 4 + i];
    }
    const float inv_scale = 0.08838834764831845f;  // 1/sqrt(128)
    int d0 = lane * 4;

    for (int rt = r0; rt < r1; rt += 32) {
        int nr = r1 - rt; if (nr > 32) nr = 32;

        // Stage K (stride 132) and V (stride 128); zero-fill tail.
#pragma unroll
        for (int j = 0; j < 4; j++) {
            int idx = t + j * 256;          // 0..1023 float4 slots
            int r = idx >> 5, c4 = idx & 31;
            float4 kv, vv;
            if (r < nr) {
                kv = ((const float4*)(g_K + (rt + r) * 128))[c4];
                vv = ((const float4*)(g_V + (rt + r) * 128))[c4];
            } else {
                kv = make_float4(0.f, 0.f, 0.f, 0.f);
                vv = kv;
            }
            *(float4*)&Ks[r * 132 + c4 * 4] = kv;
            *(float4*)&Vs[r * 128 + c4 * 4] = vv;
        }
        if (t < 32) rbs[t] = (t < nr) ? residue_batch[rt + t] : -1;
        __syncthreads();

        // Scores: s[i] = Q[a_i] . K[lane], packed-pair accumulation.
        u64 s2[4];
#pragma unroll
        for (int i = 0; i < 4; i++) s2[i] = 0ull;
#pragma unroll 8
        for (int k0 = 0; k0 < 128; k0 += 4) {
            ulonglong2 k2 = *(const ulonglong2*)&Ks[lane * 132 + k0];
#pragma unroll
            for (int i = 0; i < 4; i++) {
                ulonglong2 q2 = *(const ulonglong2*)&Qs[(w * 4 + i) * 128 + k0];
                ffma2(s2[i], q2.x, k2.x);
                ffma2(s2[i], q2.y, k2.y);
            }
        }

        // Online softmax; warp owns all 32 residue scores of its 4 atom rows.
        int rbv = rbs[lane];
#pragma unroll
        for (int i = 0; i < 4; i++) {
            float slo, shi; unpack2(slo, shi, s2[i]);
            float s = slo + shi;
            float sv = (myb[i] == rbv) ? s * inv_scale : -1e30f;
            float tm = sv;
#pragma unroll
            for (int o = 16; o > 0; o >>= 1)
                tm = fmaxf(tm, __shfl_xor_sync(0xffffffffu, tm, o));
            float mnew = fmaxf(mcur[i], tm);
            float p = (sv > -1e29f) ? __expf(sv - mnew) : 0.f;
            float ps = p;
#pragma unroll
            for (int o = 16; o > 0; o >>= 1)
                ps += __shfl_xor_sync(0xffffffffu, ps, o);
            float factor = __expf(mcur[i] - mnew);   // =1 while row empty
            lsum[i] = lsum[i] * factor + ps;
            mcur[i] = mnew;
            u64 f2 = pack2(factor, factor);
            fmul2(acc[i][0], acc[i][0], f2);
            fmul2(acc[i][1], acc[i][1], f2);
            Ps2[(w * 4 + i) * 32 + lane] = pack2(p, p);   // pre-splatted
        }
        __syncwarp();   // producer == consumer warp for Ps2 rows

        // PV accumulate: lane owns dims d0..d0+3; Ps2 reads are broadcast
        // LDS.64 that feed FFMA2 directly.
#pragma unroll 8
        for (int r = 0; r < 32; r++) {
            ulonglong2 v2 = *(const ulonglong2*)&Vs[r * 128 + d0];
#pragma unroll
            for (int i = 0; i < 4; i++) {
                u64 p2 = Ps2[(w * 4 + i) * 32 + r];
                ffma2(acc[i][0], p2, v2.x);
                ffma2(acc[i][1], p2, v2.y);
            }
        }
        __syncthreads();
    }

    // Epilogue: out = atom_h + ctx (unchanged if graph had no residues).
#pragma unroll
    for (int i = 0; i < 4; i++) {
        int a = a0 + w * 4 + i;
        float4 h = ((const float4*)(atom_h + a * 128))[lane];
        float invl = (lsum[i] > 0.f) ? 1.f / lsum[i] : 0.f;
        float c0, c1, c2, c3;
        unpack2(c0, c1, acc[i][0]);
        unpack2(c2, c3, acc[i][1]);
        float4 o;
        o.x = h.x + c0 * invl;
        o.y = h.y + c1 * invl;
        o.z = h.z + c2 * invl;
        o.w = h.w + c3 * invl;
        ((float4*)(out + a * 128))[lane] = o;
    }
}

// ---------------------------------------------------------------------------
extern "C" void kernel_launch(void* const* d_in, const int* in_sizes, int n_in,
                              void* d_out, int out_size)
{
    const float* atom_h        = (const float*)d_in[0];
    const float* residue_h     = (const float*)d_in[1];
    const int*   atom_batch    = (const int*)d_in[2];
    const int*   residue_batch = (const int*)d_in[3];
    const float* W_q           = (const float*)d_in[4];
    const float* W_k           = (const float*)d_in[5];
    const float* W_v           = (const float*)d_in[6];
    float* out = (float*)d_out;

    gemm_nt_kernel<<<A_N / 32, 256>>>(atom_h, W_q, 0, residue_batch);     // Q + rseg
    gemm_nt_kernel<<<R_N / 32, 256>>>(residue_h, W_k, 1, residue_batch);  // K
    gemm_nt_kernel<<<R_N / 32, 256>>>(residue_h, W_v, 2, residue_batch);  // V

    const int SMEM = (AT * 128 + 32 * 132 + 32 * 128) * 4   // Qs,Ks,Vs
                   + AT * 32 * 8                            // Ps2 (u64)
                   + (AT + 32) * 4;                         // ab, rbs
    cudaFuncSetAttribute(attn_kernel,
                         cudaFuncAttributeMaxDynamicSharedMemorySize, SMEM);
    attn_kernel<<<A_N / AT, 256, SMEM>>>(atom_h, atom_batch, residue_batch, out);
}

// round 8
// speedup vs baseline: 2.2317x; 2.2317x over previous
#include <cuda_runtime.h>

#define A_N 16384
#define R_N 8192
#define NB  32

// Scratch (allocation-free rule: __device__ globals). 16 MB total.
__device__ __align__(256) float g_Q[A_N * 128];
__device__ __align__(256) float g_K[R_N * 128];
__device__ __align__(256) float g_V[R_N * 128];
__device__ int g_rseg[NB + 1];

typedef unsigned long long u64;
typedef unsigned int u32;

__device__ __forceinline__ void ffma2(u64& d, u64 a, u64 b) {
    asm("fma.rn.f32x2 %0, %1, %2, %0;" : "+l"(d) : "l"(a), "l"(b));
}
__device__ __forceinline__ u64 pack2(float lo, float hi) {
    u64 d;
    asm("mov.b64 %0, {%1, %2};" : "=l"(d)
        : "r"(__float_as_uint(lo)), "r"(__float_as_uint(hi)));
    return d;
}
__device__ __forceinline__ void unpack2(float& lo, float& hi, u64 v) {
    u32 a, b;
    asm("mov.b64 {%0, %1}, %2;" : "=r"(a), "=r"(b) : "l"(v));
    lo = __uint_as_float(a); hi = __uint_as_float(b);
}
__device__ __forceinline__ u32 tf32r(float x) {
    u32 y; asm("cvt.rna.tf32.f32 %0, %1;" : "=r"(y) : "f"(x)); return y;
}
// D += A(m16k8,row) * B(k8n8,col), tf32 inputs / fp32 accumulate.
__device__ __forceinline__ void mma8(float* d, u32 a0, u32 a1, u32 a2, u32 a3,
                                     u32 b0, u32 b1) {
    asm("mma.sync.aligned.m16n8k8.row.col.f32.tf32.tf32.f32 "
        "{%0,%1,%2,%3},{%4,%5,%6,%7},{%8,%9},{%0,%1,%2,%3};"
        : "+f"(d[0]), "+f"(d[1]), "+f"(d[2]), "+f"(d[3])
        : "r"(a0), "r"(a1), "r"(a2), "r"(a3), "r"(b0), "r"(b1));
}

// ---------------------------------------------------------------------------
// Projection GEMM: Out[m][n] = sum_k X[m][k] * W[n][k], N=K=128. 256 threads,
// 64-row tile; output rounded to tf32 (attn consumes it via HMMA).
// outsel==0 also computes g_rseg in block 0.
// ---------------------------------------------------------------------------
__global__ __launch_bounds__(256) void gemm_nt_kernel(
    const float* __restrict__ X, const float* __restrict__ W, int outsel,
    const int* __restrict__ rb)
{
    __shared__ __align__(16) float Ws[32][132];
    __shared__ __align__(16) float Xs[64][32];

    float* Out = (outsel == 0) ? g_Q : (outsel == 1) ? g_K : g_V;

    int t = threadIdx.x, lane = t & 31, w = t >> 5;
    int row0 = blockIdx.x * 64;

    u64 acc[8][2];
#pragma unroll
    for (int i = 0; i < 8; i++) { acc[i][0] = 0ull; acc[i][1] = 0ull; }

    for (int kc = 0; kc < 128; kc += 32) {
#pragma unroll
        for (int j = 0; j < 16; j++) {
            int idx = t + j * 256, n = idx >> 5, kk = idx & 31;
            Ws[kk][n] = W[n * 128 + kc + kk];
        }
#pragma unroll
        for (int j = 0; j < 8; j++) {
            int idx = t + j * 256, row = idx >> 5, kk = idx & 31;
            Xs[row][kk] = X[(row0 + row) * 128 + kc + kk];
        }
        __syncthreads();
#pragma unroll 8
        for (int kk = 0; kk < 32; kk++) {
            ulonglong2 w2 = *(const ulonglong2*)&Ws[kk][lane * 4];
#pragma unroll
            for (int i = 0; i < 8; i++) {
                float x = Xs[w * 8 + i][kk];
                u64 x2 = pack2(x, x);
                ffma2(acc[i][0], x2, w2.x);
                ffma2(acc[i][1], x2, w2.y);
            }
        }
        __syncthreads();
    }

#pragma unroll
    for (int i = 0; i < 8; i++) {
        float c0, c1, c2, c3;
        unpack2(c0, c1, acc[i][0]);
        unpack2(c2, c3, acc[i][1]);
        uint4 o;   // tf32-rounded bit patterns
        o.x = tf32r(c0); o.y = tf32r(c1); o.z = tf32r(c2); o.w = tf32r(c3);
        *(uint4*)&Out[(row0 + w * 8 + i) * 128 + lane * 4] = o;
    }

    if (outsel == 0 && blockIdx.x == 0 && t <= NB) {
        int b = t, lo = 0, hi = R_N;
        while (lo < hi) {
            int mid = (lo + hi) >> 1;
            if (rb[mid] < b) lo = mid + 1; else hi = mid;
        }
        g_rseg[b] = lo;
    }
}

// ---------------------------------------------------------------------------
// Flash attention via mma.sync m16n8k8 tf32.
// 64 atoms/block, 128 threads (4 warps); warp w owns atom rows w*16..w*16+15.
// 32-residue K/V tiles. Smem strides chosen for conflict-free fragment LDS.
// ---------------------------------------------------------------------------
#define QSS 132   // Qs/Ks row stride (floats)
#define VSS 136   // Vs row stride
#define PSS 36    // Ps row stride

__global__ __launch_bounds__(128, 2) void attn_kernel(
    const float* __restrict__ atom_h,
    const int* __restrict__ atom_batch,
    const int* __restrict__ residue_batch,
    float* __restrict__ out)
{
    extern __shared__ float sm[];
    float* Qs = sm;                    // 64*132
    float* Ks = Qs + 64 * QSS;         // 32*132
    float* Vs = Ks + 32 * QSS;         // 32*136
    float* Ps = Vs + 32 * VSS;         // 64*36
    int*   ab  = (int*)(Ps + 64 * PSS);
    int*   rbs = ab + 64;

    const u32* Qsu = (const u32*)Qs;
    const u32* Ksu = (const u32*)Ks;
    const u32* Vsu = (const u32*)Vs;
    const u32* Psu = (const u32*)Ps;

    int t = threadIdx.x, lane = t & 31, w = t >> 5;
    int g = lane >> 2, tg = lane & 3;
    int a0 = blockIdx.x * 64;

    // Stage Q tile (tf32-rounded already) into stride-132 smem.
#pragma unroll
    for (int j = 0; j < 16; j++) {
        int idx = t + j * 128, row = idx >> 5, c4 = idx & 31;
        *(float4*)&Qs[row * QSS + c4 * 4] =
            ((const float4*)(g_Q + (a0 + row) * 128))[c4];
    }
    if (t < 64) ab[t] = atom_batch[a0 + t];
    __syncthreads();

    int r0 = g_rseg[ab[0]];
    int r1 = g_rseg[ab[63] + 1];

    int rowlo = w * 16 + g, rowhi = rowlo + 8;
    int blo = ab[rowlo], bhi = ab[rowhi];

    float cf[16][4];
#pragma unroll
    for (int n = 0; n < 16; n++)
#pragma unroll
        for (int j = 0; j < 4; j++) cf[n][j] = 0.f;
    float mlo = -1e30f, mhi = -1e30f, llo = 0.f, lhi = 0.f;
    const float inv_scale = 0.08838834764831845f;  // 1/sqrt(128)

    for (int rt = r0; rt < r1; rt += 32) {
        int nr = r1 - rt; if (nr > 32) nr = 32;

        // Stage K (stride 132) and V (stride 136); zero-fill tails (V zeros
        // are load-bearing: p=0 * garbage would NaN in HMMA).
#pragma unroll
        for (int j = 0; j < 8; j++) {
            int idx = t + j * 128, r = idx >> 5, c4 = idx & 31;
            float4 kv, vv;
            if (r < nr) {
                kv = ((const float4*)(g_K + (rt + r) * 128))[c4];
                vv = ((const float4*)(g_V + (rt + r) * 128))[c4];
            } else {
                kv = make_float4(0.f, 0.f, 0.f, 0.f);
                vv = kv;
            }
            *(float4*)&Ks[r * QSS + c4 * 4] = kv;
            *(float4*)&Vs[r * VSS + c4 * 4] = vv;
        }
        if (t < 32) rbs[t] = (t < nr) ? residue_batch[rt + t] : -1;
        __syncthreads();

        // ---- Scores: S(16x32) = Q(16x128) * K^T, 16 k-steps, 4 n8-frags ----
        float sf[4][4];
#pragma unroll
        for (int n = 0; n < 4; n++)
#pragma unroll
            for (int j = 0; j < 4; j++) sf[n][j] = 0.f;

        int qlo = rowlo * QSS, qhi = rowhi * QSS;
#pragma unroll
        for (int kk = 0; kk < 16; kk++) {
            int kc = kk * 8 + tg;
            u32 A0 = Qsu[qlo + kc], A1 = Qsu[qhi + kc];
            u32 A2 = Qsu[qlo + kc + 4], A3 = Qsu[qhi + kc + 4];
#pragma unroll
            for (int n = 0; n < 4; n++) {
                u32 B0 = Ksu[(8 * n + g) * QSS + kc];
                u32 B1 = Ksu[(8 * n + g) * QSS + kc + 4];
                mma8(sf[n], A0, A1, A2, A3, B0, B1);
            }
        }

        // ---- Mask + online softmax (frag rows: lo=g, hi=g+8; cols 8n+2tg) --
        float tmlo = -1e30f, tmhi = -1e30f;
#pragma unroll
        for (int n = 0; n < 4; n++) {
            int2 rb2 = *(const int2*)&rbs[n * 8 + 2 * tg];
            sf[n][0] = (rb2.x == blo) ? sf[n][0] * inv_scale : -1e30f;
            sf[n][1] = (rb2.y == blo) ? sf[n][1] * inv_scale : -1e30f;
            sf[n][2] = (rb2.x == bhi) ? sf[n][2] * inv_scale : -1e30f;
            sf[n][3] = (rb2.y == bhi) ? sf[n][3] * inv_scale : -1e30f;
            tmlo = fmaxf(tmlo, fmaxf(sf[n][0], sf[n][1]));
            tmhi = fmaxf(tmhi, fmaxf(sf[n][2], sf[n][3]));
        }
        tmlo = fmaxf(tmlo, __shfl_xor_sync(0xffffffffu, tmlo, 1));
        tmlo = fmaxf(tmlo, __shfl_xor_sync(0xffffffffu, tmlo, 2));
        tmhi = fmaxf(tmhi, __shfl_xor_sync(0xffffffffu, tmhi, 1));
        tmhi = fmaxf(tmhi, __shfl_xor_sync(0xffffffffu, tmhi, 2));

        float mnlo = fmaxf(mlo, tmlo), mnhi = fmaxf(mhi, tmhi);
        float slo = 0.f, shi = 0.f;
#pragma unroll
        for (int n = 0; n < 4; n++) {
            sf[n][0] = (sf[n][0] > -1e29f) ? __expf(sf[n][0] - mnlo) : 0.f;
            sf[n][1] = (sf[n][1] > -1e29f) ? __expf(sf[n][1] - mnlo) : 0.f;
            sf[n][2] = (sf[n][2] > -1e29f) ? __expf(sf[n][2] - mnhi) : 0.f;
            sf[n][3] = (sf[n][3] > -1e29f) ? __expf(sf[n][3] - mnhi) : 0.f;
            slo += sf[n][0] + sf[n][1];
            shi += sf[n][2] + sf[n][3];
        }
        slo += __shfl_xor_sync(0xffffffffu, slo, 1);
        slo += __shfl_xor_sync(0xffffffffu, slo, 2);
        shi += __shfl_xor_sync(0xffffffffu, shi, 1);
        shi += __shfl_xor_sync(0xffffffffu, shi, 2);

        float flo = __expf(mlo - mnlo), fhi = __expf(mhi - mnhi);
        llo = llo * flo + slo;
        lhi = lhi * fhi + shi;
        mlo = mnlo; mhi = mnhi;

#pragma unroll
        for (int n = 0; n < 16; n++) {
            cf[n][0] *= flo; cf[n][1] *= flo;
            cf[n][2] *= fhi; cf[n][3] *= fhi;
        }

        // Store P (tf32-rounded) for the PV A-fragments (own rows only).
#pragma unroll
        for (int n = 0; n < 4; n++) {
            u64 plo2 = pack2(__uint_as_float(tf32r(sf[n][0])),
                             __uint_as_float(tf32r(sf[n][1])));
            u64 phi2 = pack2(__uint_as_float(tf32r(sf[n][2])),
                             __uint_as_float(tf32r(sf[n][3])));
            *(u64*)&Ps[rowlo * PSS + 8 * n + 2 * tg] = plo2;
            *(u64*)&Ps[rowhi * PSS + 8 * n + 2 * tg] = phi2;
        }
        __syncwarp();   // each warp reads back only its own Ps rows

        // ---- PV: C(16x128) += P(16x32) * V(32x128), 4 k-steps, 16 n8 ------
#pragma unroll
        for (int kk = 0; kk < 4; kk++) {
            int kc = kk * 8 + tg;
            u32 A0 = Psu[rowlo * PSS + kc], A1 = Psu[rowhi * PSS + kc];
            u32 A2 = Psu[rowlo * PSS + kc + 4], A3 = Psu[rowhi * PSS + kc + 4];
#pragma unroll
            for (int n = 0; n < 16; n++) {
                u32 B0 = Vsu[kc * VSS + 8 * n + g];
                u32 B1 = Vsu[(kc + 4) * VSS + 8 * n + g];
                mma8(cf[n], A0, A1, A2, A3, B0, B1);
            }
        }
        __syncthreads();   // before next tile overwrites Ks/Vs
    }

    // Epilogue: out = atom_h + ctx/l (unchanged if graph had no residues).
    float invlo = (llo > 0.f) ? 1.f / llo : 0.f;
    float invhi = (lhi > 0.f) ? 1.f / lhi : 0.f;
    int alo = a0 + rowlo, ahi = a0 + rowhi;
#pragma unroll
    for (int n = 0; n < 16; n++) {
        int col = 8 * n + 2 * tg;
        float2 h = *(const float2*)&atom_h[alo * 128 + col];
        float2 o;
        o.x = h.x + cf[n][0] * invlo;
        o.y = h.y + cf[n][1] * invlo;
        *(float2*)&out[alo * 128 + col] = o;
        h = *(const float2*)&atom_h[ahi * 128 + col];
        o.x = h.x + cf[n][2] * invhi;
        o.y = h.y + cf[n][3] * invhi;
        *(float2*)&out[ahi * 128 + col] = o;
    }
}

// ---------------------------------------------------------------------------
extern "C" void kernel_launch(void* const* d_in, const int* in_sizes, int n_in,
                              void* d_out, int out_size)
{
    const float* atom_h        = (const float*)d_in[0];
    const float* residue_h     = (const float*)d_in[1];
    const int*   atom_batch    = (const int*)d_in[2];
    const int*   residue_batch = (const int*)d_in[3];
    const float* W_q           = (const float*)d_in[4];
    const float* W_k           = (const float*)d_in[5];
    const float* W_v           = (const float*)d_in[6];
    float* out = (float*)d_out;

    gemm_nt_kernel<<<A_N / 64, 256>>>(atom_h, W_q, 0, residue_batch);     // Q + rseg
    gemm_nt_kernel<<<R_N / 64, 256>>>(residue_h, W_k, 1, residue_batch);  // K
    gemm_nt_kernel<<<R_N / 64, 256>>>(residue_h, W_v, 2, residue_batch);  // V

    const int SMEM = (64 * QSS + 32 * QSS + 32 * VSS + 64 * PSS) * 4
                   + (64 + 32) * 4;
    cudaFuncSetAttribute(attn_kernel,
                         cudaFuncAttributeMaxDynamicSharedMemorySize, SMEM);
    attn_kernel<<<A_N / 64, 128, SMEM>>>(atom_h, atom_batch, residue_batch, out);
}

// round 9
// speedup vs baseline: 2.9916x; 1.3405x over previous
#include <cuda_runtime.h>

#define A_N 16384
#define R_N 8192
#define NB  32

// Scratch (allocation-free rule: __device__ globals). 16 MB total.
__device__ __align__(256) float g_Q[A_N * 128];
__device__ __align__(256) float g_K[R_N * 128];
__device__ __align__(256) float g_V[R_N * 128];
__device__ int g_rseg[NB + 1];

typedef unsigned long long u64;
typedef unsigned int u32;

__device__ __forceinline__ u64 pack2(float lo, float hi) {
    u64 d;
    asm("mov.b64 %0, {%1, %2};" : "=l"(d)
        : "r"(__float_as_uint(lo)), "r"(__float_as_uint(hi)));
    return d;
}
__device__ __forceinline__ u32 tf32r(float x) {
    u32 y; asm("cvt.rna.tf32.f32 %0, %1;" : "=r"(y) : "f"(x)); return y;
}
// D += A(m16k8,row) * B(k8n8,col), tf32 in / fp32 accumulate.
__device__ __forceinline__ void mma8(float* d, u32 a0, u32 a1, u32 a2, u32 a3,
                                     u32 b0, u32 b1) {
    asm("mma.sync.aligned.m16n8k8.row.col.f32.tf32.tf32.f32 "
        "{%0,%1,%2,%3},{%4,%5,%6,%7},{%8,%9},{%0,%1,%2,%3};"
        : "+f"(d[0]), "+f"(d[1]), "+f"(d[2]), "+f"(d[3])
        : "r"(a0), "r"(a1), "r"(a2), "r"(a3), "r"(b0), "r"(b1));
}
__device__ __forceinline__ u32 smem_u32(const void* p) {
    return (u32)__cvta_generic_to_shared(p);
}
__device__ __forceinline__ void cp16(u32 dst, const void* src) {
    asm volatile("cp.async.cg.shared.global [%0], [%1], 16;"
                 :: "r"(dst), "l"(src));
}
__device__ __forceinline__ void cp4(u32 dst, const void* src) {
    asm volatile("cp.async.ca.shared.global [%0], [%1], 4;"
                 :: "r"(dst), "l"(src));
}
#define CP_COMMIT asm volatile("cp.async.commit_group;" ::: "memory")
#define CP_WAIT1  asm volatile("cp.async.wait_group 1;"  ::: "memory")

// ---------------------------------------------------------------------------
// Tensor-core projection: Out[m][n] = sum_k X[m][k]*W[n][k], N=K=128.
// 128 threads (4 warps), 64-row tile, k in 32-chunks. Stride 44 smem gives
// conflict-free frags (banks 12g+tg mod 32 unique) and 16B-aligned rows.
// outsel==0 also computes g_rseg in block 0.
// ---------------------------------------------------------------------------
__global__ __launch_bounds__(128) void gemm_tc_kernel(
    const float* __restrict__ X, const float* __restrict__ W, int outsel,
    const int* __restrict__ rb)
{
    __shared__ __align__(16) u32 Xs[64 * 44];
    __shared__ __align__(16) u32 Ws[128 * 44];

    float* Out = (outsel == 0) ? g_Q : (outsel == 1) ? g_K : g_V;

    int t = threadIdx.x, lane = t & 31, w = t >> 5;
    int g = lane >> 2, tg = lane & 3;
    int row0 = blockIdx.x * 64;
    int rowlo = w * 16 + g, rowhi = rowlo + 8;

    float cf[16][4];
#pragma unroll
    for (int n = 0; n < 16; n++)
#pragma unroll
        for (int j = 0; j < 4; j++) cf[n][j] = 0.f;

#pragma unroll
    for (int kc = 0; kc < 128; kc += 32) {
        // Stage X chunk (64 x 32) tf32-rounded.
#pragma unroll
        for (int j = 0; j < 4; j++) {
            int idx = t + j * 128, row = idx >> 3, c4 = idx & 7;
            float4 v = *(const float4*)&X[(row0 + row) * 128 + kc + c4 * 4];
            uint4 o; o.x = tf32r(v.x); o.y = tf32r(v.y);
            o.z = tf32r(v.z); o.w = tf32r(v.w);
            *(uint4*)&Xs[row * 44 + c4 * 4] = o;
        }
        // Stage W chunk (128 x 32) tf32-rounded.
#pragma unroll
        for (int j = 0; j < 8; j++) {
            int idx = t + j * 128, row = idx >> 3, c4 = idx & 7;
            float4 v = *(const float4*)&W[row * 128 + kc + c4 * 4];
            uint4 o; o.x = tf32r(v.x); o.y = tf32r(v.y);
            o.z = tf32r(v.z); o.w = tf32r(v.w);
            *(uint4*)&Ws[row * 44 + c4 * 4] = o;
        }
        __syncthreads();

#pragma unroll
        for (int kk = 0; kk < 4; kk++) {
            int kcc = kk * 8 + tg;
            u32 A0 = Xs[rowlo * 44 + kcc], A1 = Xs[rowhi * 44 + kcc];
            u32 A2 = Xs[rowlo * 44 + kcc + 4], A3 = Xs[rowhi * 44 + kcc + 4];
#pragma unroll
            for (int n = 0; n < 16; n++) {
                u32 B0 = Ws[(8 * n + g) * 44 + kcc];
                u32 B1 = Ws[(8 * n + g) * 44 + kcc + 4];
                mma8(cf[n], A0, A1, A2, A3, B0, B1);
            }
        }
        __syncthreads();
    }

    // Epilogue: tf32-rounded outputs (attn consumes via HMMA).
#pragma unroll
    for (int n = 0; n < 16; n++) {
        int col = 8 * n + 2 * tg;
        u64 lo2 = pack2(__uint_as_float(tf32r(cf[n][0])),
                        __uint_as_float(tf32r(cf[n][1])));
        u64 hi2 = pack2(__uint_as_float(tf32r(cf[n][2])),
                        __uint_as_float(tf32r(cf[n][3])));
        *(u64*)&Out[(row0 + rowlo) * 128 + col] = lo2;
        *(u64*)&Out[(row0 + rowhi) * 128 + col] = hi2;
    }

    if (outsel == 0 && blockIdx.x == 0 && t <= NB) {
        int b = t, lo = 0, hi = R_N;
        while (lo < hi) {
            int mid = (lo + hi) >> 1;
            if (rb[mid] < b) lo = mid + 1; else hi = mid;
        }
        g_rseg[b] = lo;
    }
}

// ---------------------------------------------------------------------------
// Flash attention, m16n8k8 tf32, cp.async double-buffered K/V tiles.
// 64 atoms/block, 128 threads; warp w owns rows w*16..w*16+15.
// ---------------------------------------------------------------------------
#define QSS 132   // Qs/Ks row stride
#define VSS 136   // Vs row stride
#define PSS 36    // Ps row stride

__global__ __launch_bounds__(128, 2) void attn_kernel(
    const float* __restrict__ atom_h,
    const int* __restrict__ atom_batch,
    const int* __restrict__ residue_batch,
    float* __restrict__ out)
{
    extern __shared__ float sm[];
    float* Qs  = sm;                       // 64*132
    float* Ks0 = Qs + 64 * QSS;            // 2 x 32*132
    float* Vs0 = Ks0 + 2 * 32 * QSS;       // 2 x 32*136
    float* Ps  = Vs0 + 2 * 32 * VSS;       // 64*36
    int*   ab  = (int*)(Ps + 64 * PSS);    // 64
    int*   rbs0 = ab + 64;                 // 2 x 32

    int t = threadIdx.x, lane = t & 31, w = t >> 5;
    int g = lane >> 2, tg = lane & 3;
    int a0 = blockIdx.x * 64;

    // Stage Q tile (tf32-rounded already by projection).
#pragma unroll
    for (int j = 0; j < 16; j++) {
        int idx = t + j * 128, row = idx >> 5, c4 = idx & 31;
        *(float4*)&Qs[row * QSS + c4 * 4] =
            ((const float4*)(g_Q + (a0 + row) * 128))[c4];
    }
    if (t < 64) ab[t] = atom_batch[a0 + t];
    // Zero V buffers once: stale tail rows must stay finite (p=0*finite=0).
#pragma unroll
    for (int j = 0; j < 17; j++) {
        int idx = t + j * 128;
        if (idx < 2 * 32 * VSS / 4)
            ((float4*)Vs0)[idx] = make_float4(0.f, 0.f, 0.f, 0.f);
    }
    __syncthreads();

    int r0 = g_rseg[ab[0]];
    int r1 = g_rseg[ab[63] + 1];

    int rowlo = w * 16 + g, rowhi = rowlo + 8;
    int blo = ab[rowlo], bhi = ab[rowhi];

    float cf[16][4];
#pragma unroll
    for (int n = 0; n < 16; n++)
#pragma unroll
        for (int j = 0; j < 4; j++) cf[n][j] = 0.f;
    float mlo = -1e30f, mhi = -1e30f, llo = 0.f, lhi = 0.f;
    const float inv_scale = 0.08838834764831845f;  // 1/sqrt(128)

    const u32* Qsu = (const u32*)Qs;
    const u32* Psu = (const u32*)Ps;
    int qlo = rowlo * QSS, qhi = rowhi * QSS;

    // Prefetch helper: tile at rt2 into buffer b.
    auto prefetch = [&](int rt2, int b) {
        int nr = r1 - rt2; if (nr > 32) nr = 32;
        float* Ksb = Ks0 + b * 32 * QSS;
        float* Vsb = Vs0 + b * 32 * VSS;
#pragma unroll
        for (int j = 0; j < 8; j++) {
            int idx = t + j * 128, r = idx >> 5, c4 = idx & 31;
            if (r < nr) {
                cp16(smem_u32(&Ksb[r * QSS + c4 * 4]),
                     g_K + (rt2 + r) * 128 + c4 * 4);
                cp16(smem_u32(&Vsb[r * VSS + c4 * 4]),
                     g_V + (rt2 + r) * 128 + c4 * 4);
            }
        }
        if (t < 32 && rt2 + t < r1)
            cp4(smem_u32(&rbs0[b * 32 + t]), residue_batch + rt2 + t);
    };

    if (r0 < r1) prefetch(r0, 0);
    CP_COMMIT;

    int buf = 0;
    for (int rt = r0; rt < r1; rt += 32, buf ^= 1) {
        if (rt + 32 < r1) prefetch(rt + 32, buf ^ 1);
        CP_COMMIT;
        CP_WAIT1;
        __syncthreads();

        const u32* Ksu = (const u32*)(Ks0 + buf * 32 * QSS);
        const u32* Vsu = (const u32*)(Vs0 + buf * 32 * VSS);
        const int* rbs = rbs0 + buf * 32;
        int lim = r1 - rt;   // cols >= lim are stale: mask by bound check

        // ---- Scores: S(16x32) = Q(16x128)*K^T, 16 k-steps, 4 n8-frags ----
        float sf[4][4];
#pragma unroll
        for (int n = 0; n < 4; n++)
#pragma unroll
            for (int j = 0; j < 4; j++) sf[n][j] = 0.f;
#pragma unroll
        for (int kk = 0; kk < 16; kk++) {
            int kc = kk * 8 + tg;
            u32 A0 = Qsu[qlo + kc], A1 = Qsu[qhi + kc];
            u32 A2 = Qsu[qlo + kc + 4], A3 = Qsu[qhi + kc + 4];
#pragma unroll
            for (int n = 0; n < 4; n++) {
                u32 B0 = Ksu[(8 * n + g) * QSS + kc];
                u32 B1 = Ksu[(8 * n + g) * QSS + kc + 4];
                mma8(sf[n], A0, A1, A2, A3, B0, B1);
            }
        }

        // ---- Mask + online softmax (rows lo=g, hi=g+8; cols 8n+2tg) -------
        float tmlo = -1e30f, tmhi = -1e30f;
#pragma unroll
        for (int n = 0; n < 4; n++) {
            int c0 = n * 8 + 2 * tg;
            int2 rb2 = *(const int2*)&rbs[c0];
            bool v0 = (c0 < lim), v1 = (c0 + 1 < lim);
            sf[n][0] = (v0 && rb2.x == blo) ? sf[n][0] * inv_scale : -1e30f;
            sf[n][1] = (v1 && rb2.y == blo) ? sf[n][1] * inv_scale : -1e30f;
            sf[n][2] = (v0 && rb2.x == bhi) ? sf[n][2] * inv_scale : -1e30f;
            sf[n][3] = (v1 && rb2.y == bhi) ? sf[n][3] * inv_scale : -1e30f;
            tmlo = fmaxf(tmlo, fmaxf(sf[n][0], sf[n][1]));
            tmhi = fmaxf(tmhi, fmaxf(sf[n][2], sf[n][3]));
        }
        tmlo = fmaxf(tmlo, __shfl_xor_sync(0xffffffffu, tmlo, 1));
        tmlo = fmaxf(tmlo, __shfl_xor_sync(0xffffffffu, tmlo, 2));
        tmhi = fmaxf(tmhi, __shfl_xor_sync(0xffffffffu, tmhi, 1));
        tmhi = fmaxf(tmhi, __shfl_xor_sync(0xffffffffu, tmhi, 2));

        float mnlo = fmaxf(mlo, tmlo), mnhi = fmaxf(mhi, tmhi);
        float slo = 0.f, shi = 0.f;
#pragma unroll
        for (int n = 0; n < 4; n++) {
            sf[n][0] = (sf[n][0] > -1e29f) ? __expf(sf[n][0] - mnlo) : 0.f;
            sf[n][1] = (sf[n][1] > -1e29f) ? __expf(sf[n][1] - mnlo) : 0.f;
            sf[n][2] = (sf[n][2] > -1e29f) ? __expf(sf[n][2] - mnhi) : 0.f;
            sf[n][3] = (sf[n][3] > -1e29f) ? __expf(sf[n][3] - mnhi) : 0.f;
            slo += sf[n][0] + sf[n][1];
            shi += sf[n][2] + sf[n][3];
        }
        slo += __shfl_xor_sync(0xffffffffu, slo, 1);
        slo += __shfl_xor_sync(0xffffffffu, slo, 2);
        shi += __shfl_xor_sync(0xffffffffu, shi, 1);
        shi += __shfl_xor_sync(0xffffffffu, shi, 2);

        float flo = __expf(mlo - mnlo), fhi = __expf(mhi - mnhi);
        llo = llo * flo + slo;
        lhi = lhi * fhi + shi;
        mlo = mnlo; mhi = mnhi;
#pragma unroll
        for (int n = 0; n < 16; n++) {
            cf[n][0] *= flo; cf[n][1] *= flo;
            cf[n][2] *= fhi; cf[n][3] *= fhi;
        }

        // Store P (tf32) for PV A-frags (warp-private rows).
#pragma unroll
        for (int n = 0; n < 4; n++) {
            u64 plo2 = pack2(__uint_as_float(tf32r(sf[n][0])),
                             __uint_as_float(tf32r(sf[n][1])));
            u64 phi2 = pack2(__uint_as_float(tf32r(sf[n][2])),
                             __uint_as_float(tf32r(sf[n][3])));
            *(u64*)&Ps[rowlo * PSS + 8 * n + 2 * tg] = plo2;
            *(u64*)&Ps[rowhi * PSS + 8 * n + 2 * tg] = phi2;
        }
        __syncwarp();

        // ---- PV: C(16x128) += P(16x32)*V(32x128), 4 k-steps, 16 n8 --------
#pragma unroll
        for (int kk = 0; kk < 4; kk++) {
            int kc = kk * 8 + tg;
            u32 A0 = Psu[rowlo * PSS + kc], A1 = Psu[rowhi * PSS + kc];
            u32 A2 = Psu[rowlo * PSS + kc + 4], A3 = Psu[rowhi * PSS + kc + 4];
#pragma unroll
            for (int n = 0; n < 16; n++) {
                u32 B0 = Vsu[kc * VSS + 8 * n + g];
                u32 B1 = Vsu[(kc + 4) * VSS + 8 * n + g];
                mma8(cf[n], A0, A1, A2, A3, B0, B1);
            }
        }
        __syncthreads();   // all warps done with buf before it is refilled
    }

    // Epilogue: out = atom_h + ctx/l (rows with no residues stay unchanged).
    float invlo = (llo > 0.f) ? 1.f / llo : 0.f;
    float invhi = (lhi > 0.f) ? 1.f / lhi : 0.f;
    int alo = a0 + rowlo, ahi = a0 + rowhi;
#pragma unroll
    for (int n = 0; n < 16; n++) {
        int col = 8 * n + 2 * tg;
        float2 h = *(const float2*)&atom_h[alo * 128 + col];
        float2 o;
        o.x = h.x + cf[n][0] * invlo;
        o.y = h.y + cf[n][1] * invlo;
        *(float2*)&out[alo * 128 + col] = o;
        h = *(const float2*)&atom_h[ahi * 128 + col];
        o.x = h.x + cf[n][2] * invhi;
        o.y = h.y + cf[n][3] * invhi;
        *(float2*)&out[ahi * 128 + col] = o;
    }
}

// ---------------------------------------------------------------------------
extern "C" void kernel_launch(void* const* d_in, const int* in_sizes, int n_in,
                              void* d_out, int out_size)
{
    const float* atom_h        = (const float*)d_in[0];
    const float* residue_h     = (const float*)d_in[1];
    const int*   atom_batch    = (const int*)d_in[2];
    const int*   residue_batch = (const int*)d_in[3];
    const float* W_q           = (const float*)d_in[4];
    const float* W_k           = (const float*)d_in[5];
    const float* W_v           = (const float*)d_in[6];
    float* out = (float*)d_out;

    gemm_tc_kernel<<<A_N / 64, 128>>>(atom_h, W_q, 0, residue_batch);     // Q + rseg
    gemm_tc_kernel<<<R_N / 64, 128>>>(residue_h, W_k, 1, residue_batch);  // K
    gemm_tc_kernel<<<R_N / 64, 128>>>(residue_h, W_v, 2, residue_batch);  // V

    const int SMEM = (64 * QSS + 2 * 32 * QSS + 2 * 32 * VSS + 64 * PSS) * 4
                   + (64 + 64) * 4;
    cudaFuncSetAttribute(attn_kernel,
                         cudaFuncAttributeMaxDynamicSharedMemorySize, SMEM);
    attn_kernel<<<A_N / 64, 128, SMEM>>>(atom_h, atom_batch, residue_batch, out);
}

// round 10
// speedup vs baseline: 4.7688x; 1.5941x over previous
#include <cuda_runtime.h>
#include <cuda_fp16.h>

#define A_N 16384
#define R_N 8192
#define NB  32

// Scratch (allocation-free rule: __device__ globals). fp16: 8 MB total.
__device__ __align__(256) __half g_Q[A_N * 128];
__device__ __align__(256) __half g_K[R_N * 128];
__device__ __align__(256) __half g_V[R_N * 128];
__device__ int g_rseg[NB + 1];

typedef unsigned long long u64;
typedef unsigned int u32;

// D += A(m16k16,row,f16) * B(k16n8,col,f16), fp32 accumulate.
__device__ __forceinline__ void mma16(float* d, u32 a0, u32 a1, u32 a2, u32 a3,
                                      u32 b0, u32 b1) {
    asm("mma.sync.aligned.m16n8k16.row.col.f32.f16.f16.f32 "
        "{%0,%1,%2,%3},{%4,%5,%6,%7},{%8,%9},{%0,%1,%2,%3};"
        : "+f"(d[0]), "+f"(d[1]), "+f"(d[2]), "+f"(d[3])
        : "r"(a0), "r"(a1), "r"(a2), "r"(a3), "r"(b0), "r"(b1));
}
// Transposed 8x8 b16 quad-load: B-frags for two n8 blocks from row-major V.
__device__ __forceinline__ void ldsm4t(u32& r0, u32& r1, u32& r2, u32& r3,
                                       u32 addr) {
    asm volatile("ldmatrix.sync.aligned.m8n8.x4.trans.shared.b16 "
                 "{%0,%1,%2,%3}, [%4];"
                 : "=r"(r0), "=r"(r1), "=r"(r2), "=r"(r3) : "r"(addr));
}
__device__ __forceinline__ u32 smem_u32(const void* p) {
    return (u32)__cvta_generic_to_shared(p);
}
__device__ __forceinline__ void cp16(u32 dst, const void* src) {
    asm volatile("cp.async.cg.shared.global [%0], [%1], 16;"
                 :: "r"(dst), "l"(src));
}
__device__ __forceinline__ void cp4(u32 dst, const void* src) {
    asm volatile("cp.async.ca.shared.global [%0], [%1], 4;"
                 :: "r"(dst), "l"(src));
}
#define CP_COMMIT asm volatile("cp.async.commit_group;" ::: "memory")
#define CP_WAIT1  asm volatile("cp.async.wait_group 1;"  ::: "memory")

__device__ __forceinline__ u32 h2u(__half2 h) { return *(u32*)&h; }

// ---------------------------------------------------------------------------
// Merged fp16-HMMA projections: one launch, grid 512.
//   blocks [0,256): Q = atom_h@Wq^T; [256,384): K; [384,512): V.
// 128 threads, 64-row tile, k in 32-chunks (2 k16 steps each).
// Stride-40-half smem => conflict-free frags (20g+tg distinct mod 32).
// Block 0 also computes g_rseg.
// ---------------------------------------------------------------------------
__global__ __launch_bounds__(128) void proj_kernel(
    const float* __restrict__ atom_h, const float* __restrict__ residue_h,
    const float* __restrict__ W_q, const float* __restrict__ W_k,
    const float* __restrict__ W_v, const int* __restrict__ rb)
{
    __shared__ __align__(16) __half Xs[64 * 40];
    __shared__ __align__(16) __half Ws[128 * 40];

    int bx = blockIdx.x;
    const float* X; const float* W; __half* Out; int row0;
    if (bx < 256)      { X = atom_h;    W = W_q; Out = g_Q; row0 = bx * 64; }
    else if (bx < 384) { X = residue_h; W = W_k; Out = g_K; row0 = (bx - 256) * 64; }
    else               { X = residue_h; W = W_v; Out = g_V; row0 = (bx - 384) * 64; }

    int t = threadIdx.x, lane = t & 31, w = t >> 5;
    int g = lane >> 2, tg = lane & 3;
    int rowlo = w * 16 + g, rowhi = rowlo + 8;

    const u32* Xsu = (const u32*)Xs;
    const u32* Wsu = (const u32*)Ws;

    float cf[16][4];
#pragma unroll
    for (int n = 0; n < 16; n++)
#pragma unroll
        for (int j = 0; j < 4; j++) cf[n][j] = 0.f;

#pragma unroll
    for (int kc = 0; kc < 128; kc += 32) {
#pragma unroll
        for (int j = 0; j < 4; j++) {          // X chunk: 64x32 fp32 -> half
            int idx = t + j * 128, row = idx >> 3, c4 = idx & 7;
            float4 v = *(const float4*)&X[(row0 + row) * 128 + kc + c4 * 4];
            uint2 o; o.x = h2u(__floats2half2_rn(v.x, v.y));
            o.y = h2u(__floats2half2_rn(v.z, v.w));
            *(uint2*)&Xs[row * 40 + c4 * 4] = o;
        }
#pragma unroll
        for (int j = 0; j < 8; j++) {          // W chunk: 128x32 fp32 -> half
            int idx = t + j * 128, row = idx >> 3, c4 = idx & 7;
            float4 v = *(const float4*)&W[row * 128 + kc + c4 * 4];
            uint2 o; o.x = h2u(__floats2half2_rn(v.x, v.y));
            o.y = h2u(__floats2half2_rn(v.z, v.w));
            *(uint2*)&Ws[row * 40 + c4 * 4] = o;
        }
        __syncthreads();

#pragma unroll
        for (int kk = 0; kk < 2; kk++) {
            int kb = 8 * kk + tg;
            u32 A0 = Xsu[rowlo * 20 + kb],     A1 = Xsu[rowhi * 20 + kb];
            u32 A2 = Xsu[rowlo * 20 + kb + 4], A3 = Xsu[rowhi * 20 + kb + 4];
#pragma unroll
            for (int n = 0; n < 16; n++) {
                u32 B0 = Wsu[(8 * n + g) * 20 + kb];
                u32 B1 = Wsu[(8 * n + g) * 20 + kb + 4];
                mma16(cf[n], A0, A1, A2, A3, B0, B1);
            }
        }
        __syncthreads();
    }

#pragma unroll
    for (int n = 0; n < 16; n++) {
        int col = 8 * n + 2 * tg;
        *(u32*)&Out[(row0 + rowlo) * 128 + col] =
            h2u(__floats2half2_rn(cf[n][0], cf[n][1]));
        *(u32*)&Out[(row0 + rowhi) * 128 + col] =
            h2u(__floats2half2_rn(cf[n][2], cf[n][3]));
    }

    if (bx == 0 && t <= NB) {
        int b = t, lo = 0, hi = R_N;
        while (lo < hi) {
            int mid = (lo + hi) >> 1;
            if (rb[mid] < b) lo = mid + 1; else hi = mid;
        }
        g_rseg[b] = lo;
    }
}

// ---------------------------------------------------------------------------
// Flash attention, fp16 m16n8k16, cp.async double-buffered K/V.
// 64 atoms/block, 128 threads; warp w owns rows w*16..w*16+15.
// V consumed via ldmatrix.x4.trans (row-major -> B-frags).
// ---------------------------------------------------------------------------
#define QH 136   // half stride for Qs/Ks/Vs rows (68 u32, 4 mod 32)
#define PH 40    // half stride for Ps rows (20 u32)

#define QS_BYTES (64 * QH * 2)
#define KS_BYTES (2 * 32 * QH * 2)
#define VS_BYTES (2 * 32 * QH * 2)
#define PS_BYTES (64 * PH * 2)
#define SMEM_ATTN (QS_BYTES + KS_BYTES + VS_BYTES + PS_BYTES + 64*4 + 64*4)

__global__ __launch_bounds__(128, 3) void attn_kernel(
    const float* __restrict__ atom_h,
    const int* __restrict__ atom_batch,
    const int* __restrict__ residue_batch,
    float* __restrict__ out)
{
    extern __shared__ __align__(16) char smraw[];
    __half* Qs  = (__half*)smraw;
    __half* Ks0 = (__half*)(smraw + QS_BYTES);
    __half* Vs0 = (__half*)(smraw + QS_BYTES + KS_BYTES);
    __half* Ps  = (__half*)(smraw + QS_BYTES + KS_BYTES + VS_BYTES);
    int* ab  = (int*)(smraw + QS_BYTES + KS_BYTES + VS_BYTES + PS_BYTES);
    int* rbs0 = ab + 64;

    int t = threadIdx.x, lane = t & 31, w = t >> 5;
    int g = lane >> 2, tg = lane & 3;
    int a0 = blockIdx.x * 64;

    // Stage Q tile (half): 64 rows x 128 halves, stride-QH smem.
#pragma unroll
    for (int j = 0; j < 8; j++) {
        int idx = t + j * 128, row = idx >> 4, c = idx & 15;
        *(uint4*)&Qs[row * QH + c * 8] =
            ((const uint4*)(g_Q + (size_t)(a0 + row) * 128))[c];
    }
    if (t < 64) ab[t] = atom_batch[a0 + t];
    // Zero V buffers: stale tail rows must stay finite (p=0*finite=0).
#pragma unroll
    for (int j = 0; j < 9; j++) {
        int idx = t + j * 128;
        if (idx < VS_BYTES / 16)
            ((uint4*)Vs0)[idx] = make_uint4(0, 0, 0, 0);
    }
    __syncthreads();

    int r0 = g_rseg[ab[0]];
    int r1 = g_rseg[ab[63] + 1];

    int rowlo = w * 16 + g, rowhi = rowlo + 8;
    int blo = ab[rowlo], bhi = ab[rowhi];

    float cf[16][4];
#pragma unroll
    for (int n = 0; n < 16; n++)
#pragma unroll
        for (int j = 0; j < 4; j++) cf[n][j] = 0.f;
    float mlo = -1e30f, mhi = -1e30f, llo = 0.f, lhi = 0.f;
    const float inv_scale = 0.08838834764831845f;  // 1/sqrt(128)

    const u32* Qsu = (const u32*)Qs;
    const u32* Psu = (const u32*)Ps;
    int qlo = rowlo * (QH / 2), qhi = rowhi * (QH / 2);
    int plo = rowlo * (PH / 2), phi = rowhi * (PH / 2);

    auto prefetch = [&](int rt2, int b) {
        int nr = r1 - rt2; if (nr > 32) nr = 32;
        __half* Ksb = Ks0 + b * 32 * QH;
        __half* Vsb = Vs0 + b * 32 * QH;
#pragma unroll
        for (int j = 0; j < 4; j++) {
            int idx = t + j * 128, r = idx >> 4, c = idx & 15;
            if (r < nr) {
                cp16(smem_u32(&Ksb[r * QH + c * 8]),
                     g_K + (size_t)(rt2 + r) * 128 + c * 8);
                cp16(smem_u32(&Vsb[r * QH + c * 8]),
                     g_V + (size_t)(rt2 + r) * 128 + c * 8);
            }
        }
        if (t < 32 && rt2 + t < r1)
            cp4(smem_u32(&rbs0[b * 32 + t]), residue_batch + rt2 + t);
    };

    if (r0 < r1) prefetch(r0, 0);
    CP_COMMIT;

    int buf = 0;
    for (int rt = r0; rt < r1; rt += 32, buf ^= 1) {
        if (rt + 32 < r1) prefetch(rt + 32, buf ^ 1);
        CP_COMMIT;
        CP_WAIT1;
        __syncthreads();

        const u32* Ksu = (const u32*)(Ks0 + buf * 32 * QH);
        const __half* Vsb = Vs0 + buf * 32 * QH;
        const int* rbs = rbs0 + buf * 32;
        int lim = r1 - rt;

        // ---- Scores: S(16x32) = Q(16x128)*K^T, 8 k16-steps, 4 n8-frags ----
        float sf[4][4];
#pragma unroll
        for (int n = 0; n < 4; n++)
#pragma unroll
            for (int j = 0; j < 4; j++) sf[n][j] = 0.f;
#pragma unroll
        for (int kk = 0; kk < 8; kk++) {
            int kb = 8 * kk + tg;
            u32 A0 = Qsu[qlo + kb],     A1 = Qsu[qhi + kb];
            u32 A2 = Qsu[qlo + kb + 4], A3 = Qsu[qhi + kb + 4];
#pragma unroll
            for (int n = 0; n < 4; n++) {
                u32 B0 = Ksu[(8 * n + g) * (QH / 2) + kb];
                u32 B1 = Ksu[(8 * n + g) * (QH / 2) + kb + 4];
                mma16(sf[n], A0, A1, A2, A3, B0, B1);
            }
        }

        // ---- Mask + online softmax (rows lo=g, hi=g+8; cols 8n+2tg) -------
        float tmlo = -1e30f, tmhi = -1e30f;
#pragma unroll
        for (int n = 0; n < 4; n++) {
            int c0 = n * 8 + 2 * tg;
            int2 rb2 = *(const int2*)&rbs[c0];
            bool v0 = (c0 < lim), v1 = (c0 + 1 < lim);
            sf[n][0] = (v0 && rb2.x == blo) ? sf[n][0] * inv_scale : -1e30f;
            sf[n][1] = (v1 && rb2.y == blo) ? sf[n][1] * inv_scale : -1e30f;
            sf[n][2] = (v0 && rb2.x == bhi) ? sf[n][2] * inv_scale : -1e30f;
            sf[n][3] = (v1 && rb2.y == bhi) ? sf[n][3] * inv_scale : -1e30f;
            tmlo = fmaxf(tmlo, fmaxf(sf[n][0], sf[n][1]));
            tmhi = fmaxf(tmhi, fmaxf(sf[n][2], sf[n][3]));
        }
        tmlo = fmaxf(tmlo, __shfl_xor_sync(0xffffffffu, tmlo, 1));
        tmlo = fmaxf(tmlo, __shfl_xor_sync(0xffffffffu, tmlo, 2));
        tmhi = fmaxf(tmhi, __shfl_xor_sync(0xffffffffu, tmhi, 1));
        tmhi = fmaxf(tmhi, __shfl_xor_sync(0xffffffffu, tmhi, 2));

        float mnlo = fmaxf(mlo, tmlo), mnhi = fmaxf(mhi, tmhi);
        float slo = 0.f, shi = 0.f;
#pragma unroll
        for (int n = 0; n < 4; n++) {
            sf[n][0] = (sf[n][0] > -1e29f) ? __expf(sf[n][0] - mnlo) : 0.f;
            sf[n][1] = (sf[n][1] > -1e29f) ? __expf(sf[n][1] - mnlo) : 0.f;
            sf[n][2] = (sf[n][2] > -1e29f) ? __expf(sf[n][2] - mnhi) : 0.f;
            sf[n][3] = (sf[n][3] > -1e29f) ? __expf(sf[n][3] - mnhi) : 0.f;
            slo += sf[n][0] + sf[n][1];
            shi += sf[n][2] + sf[n][3];
        }
        slo += __shfl_xor_sync(0xffffffffu, slo, 1);
        slo += __shfl_xor_sync(0xffffffffu, slo, 2);
        shi += __shfl_xor_sync(0xffffffffu, shi, 1);
        shi += __shfl_xor_sync(0xffffffffu, shi, 2);

        float flo = __expf(mlo - mnlo), fhi = __expf(mhi - mnhi);
        llo = llo * flo + slo;
        lhi = lhi * fhi + shi;
        mlo = mnlo; mhi = mnhi;
#pragma unroll
        for (int n = 0; n < 16; n++) {
            cf[n][0] *= flo; cf[n][1] *= flo;
            cf[n][2] *= fhi; cf[n][3] *= fhi;
        }

        // Store P as half2 for PV A-frags (warp-private rows).
#pragma unroll
        for (int n = 0; n < 4; n++) {
            *(u32*)&Ps[rowlo * PH + 8 * n + 2 * tg] =
                h2u(__floats2half2_rn(sf[n][0], sf[n][1]));
            *(u32*)&Ps[rowhi * PH + 8 * n + 2 * tg] =
                h2u(__floats2half2_rn(sf[n][2], sf[n][3]));
        }
        __syncwarp();

        // ---- PV: C(16x128) += P(16x32)*V(32x128), 2 k16-steps -------------
        // B-frags via ldmatrix.x4.trans on row-major V (two n8 blocks/op).
        int lrow = 16 * 0 + (lane & 15);          // k-row provided by this lane
        int lcol = (lane >> 4) << 3;              // 0 or 8: n8 sub-block
#pragma unroll
        for (int kk = 0; kk < 2; kk++) {
            int kb = 8 * kk + tg;
            u32 A0 = Psu[plo + kb],     A1 = Psu[phi + kb];
            u32 A2 = Psu[plo + kb + 4], A3 = Psu[phi + kb + 4];
            u32 base = smem_u32(&Vsb[(16 * kk + (lane & 15)) * QH + lcol]);
#pragma unroll
            for (int np = 0; np < 8; np++) {
                u32 b00, b01, b10, b11;
                ldsm4t(b00, b01, b10, b11, base + np * 32);  // 16 halves/np
                mma16(cf[2 * np],     A0, A1, A2, A3, b00, b01);
                mma16(cf[2 * np + 1], A0, A1, A2, A3, b10, b11);
            }
        }
        __syncthreads();   // all warps done with buf before it is refilled
    }

    // Epilogue: out = atom_h + ctx/l (rows with no residues stay unchanged).
    float invlo = (llo > 0.f) ? 1.f / llo : 0.f;
    float invhi = (lhi > 0.f) ? 1.f / lhi : 0.f;
    int alo = a0 + rowlo, ahi = a0 + rowhi;
#pragma unroll
    for (int n = 0; n < 16; n++) {
        int col = 8 * n + 2 * tg;
        float2 h = *(const float2*)&atom_h[(size_t)alo * 128 + col];
        float2 o;
        o.x = h.x + cf[n][0] * invlo;
        o.y = h.y + cf[n][1] * invlo;
        *(float2*)&out[(size_t)alo * 128 + col] = o;
        h = *(const float2*)&atom_h[(size_t)ahi * 128 + col];
        o.x = h.x + cf[n][2] * invhi;
        o.y = h.y + cf[n][3] * invhi;
        *(float2*)&out[(size_t)ahi * 128 + col] = o;
    }
}

// ---------------------------------------------------------------------------
extern "C" void kernel_launch(void* const* d_in, const int* in_sizes, int n_in,
                              void* d_out, int out_size)
{
    const float* atom_h        = (const float*)d_in[0];
    const float* residue_h     = (const float*)d_in[1];
    const int*   atom_batch    = (const int*)d_in[2];
    const int*   residue_batch = (const int*)d_in[3];
    const float* W_q           = (const float*)d_in[4];
    const float* W_k           = (const float*)d_in[5];
    const float* W_v           = (const float*)d_in[6];
    float* out = (float*)d_out;

    proj_kernel<<<512, 128>>>(atom_h, residue_h, W_q, W_k, W_v, residue_batch);

    cudaFuncSetAttribute(attn_kernel,
                         cudaFuncAttributeMaxDynamicSharedMemorySize, SMEM_ATTN);
    attn_kernel<<<A_N / 64, 128, SMEM_ATTN>>>(atom_h, atom_batch,
                                              residue_batch, out);
}